// round 7
// baseline (speedup 1.0000x reference)
#include <cuda_runtime.h>
#include <cuda_bf16.h>
#include <stdint.h>

#define IN_F 256
#define HF   128
#define NC   64
#define MAX_NODES 10000
#define MAX_EDGES 640000
#define PAD 192   // max supported degree; Poisson(64) tail at 192 is ~1e-60

typedef unsigned long long ull;
typedef long long ll;

#define ADD2(d, a, b) \
    asm("add.rn.f32x2 %0, %1, %2;" : "=l"(d) : "l"(a), "l"(b))
__device__ __forceinline__ void upk2(float& lo, float& hi, ull v) {
    asm("mov.b64 {%0, %1}, %2;" : "=f"(lo), "=f"(hi) : "l"(v));
}

// ---------------- scratch (static device globals; no allocation) -------------
__device__ float g_h0[MAX_NODES * HF];
__device__ float g_h1[MAX_NODES * HF];
__device__ float g_h2[MAX_NODES * HF];
__device__ float g_mean[MAX_NODES * HF];
__device__ int   g_cnt[MAX_NODES];
__device__ int   g_csr[MAX_NODES * PAD];
__device__ int   g_is64;

// Persistent split-bf16 weights
#define OFF_LIN 0
#define OFF_L1  32768
#define OFF_R1  49152
#define OFF_L2  65536
#define OFF_R2  81920
#define OFF_CLS 98304
#define TOTW    106496
__device__ __nv_bfloat16 g_Whi[TOTW];
__device__ __nv_bfloat16 g_Wlo[TOTW];

// ---------------- dtype detect -----------------------------------------------
__global__ void detect_kernel(const void* ei, long long total_elems, int n_nodes) {
    if (threadIdx.x == 0 && blockIdx.x == 0) g_is64 = 1;
    __threadfence();
    const long long* p = (const long long*)ei;
    long long nsamp = total_elems < 4096 ? total_elems : 4096;
    for (long long i = threadIdx.x; i < nsamp; i += blockDim.x) {
        long long v = p[i];
        if (v < 0 || v >= (long long)n_nodes) { g_is64 = 0; break; }
    }
}

// ---------------- padded-CSR scatter -------------------------------------------
__global__ void scatter_kernel(const void* ei, int E) {
    int e = blockIdx.x * blockDim.x + threadIdx.x;
    if (e >= E) return;
    int is64 = g_is64;
    int src, dst;
    if (is64) {
        src = (int)((const long long*)ei)[e];
        dst = (int)((const long long*)ei)[(long long)E + e];
    } else {
        src = ((const int*)ei)[e];
        dst = ((const int*)ei)[E + e];
    }
    int pos = atomicAdd(&g_cnt[dst], 1);
    if (pos < PAD) g_csr[dst * PAD + pos] = src;
}

// ---------------- weight split: fp32 -> bf16 hi + bf16 lo ---------------------
__global__ void wsplit_kernel(const float* __restrict__ wlin,
                              const float* __restrict__ wl1, const float* __restrict__ wr1,
                              const float* __restrict__ wl2, const float* __restrict__ wr2,
                              const float* __restrict__ wcls) {
    int i = blockIdx.x * blockDim.x + threadIdx.x;
    if (i >= TOTW) return;
    const float* src; int off;
    if (i < OFF_L1)       { src = wlin; off = OFF_LIN; }
    else if (i < OFF_L2)  { if (i < OFF_R1) { src = wl1; off = OFF_L1; } else { src = wr1; off = OFF_R1; } }
    else if (i < OFF_CLS) { if (i < OFF_R2) { src = wl2; off = OFF_L2; } else { src = wr2; off = OFF_R2; } }
    else                  { src = wcls; off = OFF_CLS; }
    float x = src[i - off];
    __nv_bfloat16 h = __float2bfloat16_rn(x);
    g_Whi[i] = h;
    g_Wlo[i] = __float2bfloat16_rn(x - __bfloat162float(h));
}

// ---------------- mean aggregation (pull over padded CSR, warp per node) ------
__global__ void __launch_bounds__(256, 4)
agg_kernel(const float* __restrict__ h, float* __restrict__ out, int n) {
    int warp = (blockIdx.x * blockDim.x + threadIdx.x) >> 5;
    int lane = threadIdx.x & 31;
    if (warp >= n) return;
    int deg = g_cnt[warp];
    int end = deg < PAD ? deg : PAD;
    const int* lst = &g_csr[warp * PAD];
    const ulonglong2* hb = (const ulonglong2*)h;

    ull a0 = 0, a1 = 0, b0 = 0, b1 = 0, c0 = 0, c1 = 0, d0 = 0, d1 = 0;
    int e = 0;
    for (; e + 3 < end; e += 4) {
        int j0 = lst[e], j1 = lst[e + 1], j2 = lst[e + 2], j3 = lst[e + 3];
        ulonglong2 v0 = hb[(ll)j0 * 32 + lane];
        ulonglong2 v1 = hb[(ll)j1 * 32 + lane];
        ulonglong2 v2 = hb[(ll)j2 * 32 + lane];
        ulonglong2 v3 = hb[(ll)j3 * 32 + lane];
        ADD2(a0, a0, v0.x); ADD2(a1, a1, v0.y);
        ADD2(b0, b0, v1.x); ADD2(b1, b1, v1.y);
        ADD2(c0, c0, v2.x); ADD2(c1, c1, v2.y);
        ADD2(d0, d0, v3.x); ADD2(d1, d1, v3.y);
    }
    for (; e < end; e++) {
        int j0 = lst[e];
        ulonglong2 v0 = hb[(ll)j0 * 32 + lane];
        ADD2(a0, a0, v0.x); ADD2(a1, a1, v0.y);
    }
    ADD2(a0, a0, b0); ADD2(a1, a1, b1);
    ADD2(c0, c0, d0); ADD2(c1, c1, d1);
    ADD2(a0, a0, c0); ADD2(a1, a1, c1);

    float s = 1.0f / (float)(deg > 1 ? deg : 1);
    float f0, f1, f2, f3;
    upk2(f0, f1, a0);
    upk2(f2, f3, a1);
    float4 r = make_float4(f0 * s, f1 * s, f2 * s, f3 * s);
    ((float4*)out)[(ll)warp * 32 + lane] = r;
}

// ---------------- split-bf16 tensor-core GEMM, pipelined ----------------------
// C[M,BN] = Avirt[M,KV] @ Wvirt[BN,KV]^T (+bias)(+relu), where for DUAL the
// virtual K concatenates [A1|A2] and [W1;W2] (dual-pass SAGE as one GEMM).
// A tile (32 x KV) split-loaded to smem ONCE; W streamed in 32-k chunks with
// double buffering (1 sync per chunk). 3 MMAs per k16: hh + lh + hl.
#define MMA_BF16(c, a0,a1,a2,a3, b0,b1) \
    asm volatile("mma.sync.aligned.m16n8k16.row.col.f32.bf16.bf16.f32 " \
        "{%0,%1,%2,%3}, {%4,%5,%6,%7}, {%8,%9}, {%0,%1,%2,%3};" \
        : "+f"(c[0]), "+f"(c[1]), "+f"(c[2]), "+f"(c[3]) \
        : "r"(a0), "r"(a1), "r"(a2), "r"(a3), "r"(b0), "r"(b1))

__device__ __forceinline__ uint32_t pk_hi(float a, float b, float& ra, float& rb) {
    __nv_bfloat16 ha = __float2bfloat16_rn(a), hb = __float2bfloat16_rn(b);
    ra = a - __bfloat162float(ha);
    rb = b - __bfloat162float(hb);
    return (uint32_t)__bfloat16_as_ushort(ha) | ((uint32_t)__bfloat16_as_ushort(hb) << 16);
}
__device__ __forceinline__ uint32_t pk_lo(float a, float b) {
    return (uint32_t)__bfloat16_as_ushort(__float2bfloat16_rn(a)) |
           ((uint32_t)__bfloat16_as_ushort(__float2bfloat16_rn(b)) << 16);
}

#define PADW 20   // u32 per W-chunk row (16 + 4 pad) -> conflict-free

template<int BN, int KV, bool DUAL, bool RELU_IN, bool RELU_OUT, bool HAS_BIAS>
__global__ void __launch_bounds__(256)
mma_gemm(const float* __restrict__ A1, const float* __restrict__ A2,
         int woff1, int woff2,
         const float* __restrict__ bias, float* __restrict__ C, int M) {
    const int ASTR = KV / 2 + 4;          // u32 per A row, padded
    const int ASZ  = 32 * ASTR;
    const int WBUF = BN * PADW;
    const int NCH  = KV / 32;
    const int KA   = DUAL ? KV / 2 : KV;  // physical K of A/W arrays
    const int NFRAG = BN / 32;
    const int WN    = BN / 4;

    extern __shared__ uint32_t sm[];
    uint32_t* As_hi = sm;
    uint32_t* As_lo = sm + ASZ;
    uint32_t* Wb    = sm + 2 * ASZ;       // 2 buffers x (hi | lo), each WBUF

    int tid  = threadIdx.x;
    int wid  = tid >> 5;
    int lane = tid & 31;
    int g    = lane >> 2;
    int t    = lane & 3;
    int wm   = wid >> 2;
    int wn   = wid & 3;
    int m0   = blockIdx.x * 32;

    // ---- A tile: load, relu, split, store once ------------------------------
#pragma unroll
    for (int it = 0; it < (32 * KV / 4) / 256; it++) {
        int f = tid + it * 256;
        int m  = f / (KV / 4);
        int kq = f % (KV / 4);
        int k  = kq * 4;
        const float* src = A1; int kk = k;
        if (DUAL && k >= KV / 2) { src = A2; kk = k - KV / 2; }
        float4 v = make_float4(0.f, 0.f, 0.f, 0.f);
        if (m0 + m < M)
            v = *(const float4*)&src[(ll)(m0 + m) * KA + kk];
        if (RELU_IN) {
            v.x = fmaxf(v.x, 0.f); v.y = fmaxf(v.y, 0.f);
            v.z = fmaxf(v.z, 0.f); v.w = fmaxf(v.w, 0.f);
        }
        float rx, ry, rz, rw;
        uint32_t h0 = pk_hi(v.x, v.y, rx, ry);
        uint32_t h1 = pk_hi(v.z, v.w, rz, rw);
        As_hi[m * ASTR + kq * 2 + 0] = h0;
        As_hi[m * ASTR + kq * 2 + 1] = h1;
        As_lo[m * ASTR + kq * 2 + 0] = pk_lo(rx, ry);
        As_lo[m * ASTR + kq * 2 + 1] = pk_lo(rz, rw);
    }

    // ---- W chunk fill (to buffer b): BN rows x 32 k, hi+lo ------------------
    auto fillW = [&](int c, int b) {
        uint32_t* dh = Wb + b * 2 * WBUF;
        uint32_t* dl = dh + WBUF;
#pragma unroll
        for (int it = 0; it < BN / 64; it++) {
            int f = tid + it * 256;          // BN*4 slots (uint4 of 8 bf16)
            int nn = f >> 2, q = f & 3;
            int k = c * 32 + q * 8;
            int wo = woff1; int kk = k;
            if (DUAL && k >= KV / 2) { wo = woff2; kk = k - KV / 2; }
            const ll si = (ll)nn * KA + kk + (ll)wo;
            uint4 vh = *(const uint4*)&g_Whi[si];
            uint4 vl = *(const uint4*)&g_Wlo[si];
            *(uint4*)&dh[nn * PADW + q * 4] = vh;
            *(uint4*)&dl[nn * PADW + q * 4] = vl;
        }
        if (BN == 64) {                      // BN*4 = 256 slots exactly
            int f = tid;
            int nn = f >> 2, q = f & 3;
            int k = c * 32 + q * 8;
            int wo = woff1; int kk = k;
            if (DUAL && k >= KV / 2) { wo = woff2; kk = k - KV / 2; }
            const ll si = (ll)nn * KA + kk + (ll)wo;
            uint4 vh = *(const uint4*)&g_Whi[si];
            uint4 vl = *(const uint4*)&g_Wlo[si];
            *(uint4*)&dh[nn * PADW + q * 4] = vh;
            *(uint4*)&dl[nn * PADW + q * 4] = vl;
        }
    };

    float c_[NFRAG][4];
#pragma unroll
    for (int i = 0; i < NFRAG; i++)
#pragma unroll
        for (int j = 0; j < 4; j++) c_[i][j] = 0.f;

    fillW(0, 0);
    __syncthreads();

#pragma unroll
    for (int c = 0; c < NCH; c++) {
        if (c + 1 < NCH) fillW(c + 1, (c + 1) & 1);
        const uint32_t* wh = Wb + (c & 1) * 2 * WBUF;
        const uint32_t* wl = wh + WBUF;
#pragma unroll
        for (int ko = 0; ko < 2; ko++) {
            int kb = c * 16 + ko * 8;
            int ra = (wm * 16 + g) * ASTR + kb + t;
            int rb = ra + 8 * ASTR;
            uint32_t ah0 = As_hi[ra],     ah1 = As_hi[rb];
            uint32_t ah2 = As_hi[ra + 4], ah3 = As_hi[rb + 4];
            uint32_t al0 = As_lo[ra],     al1 = As_lo[rb];
            uint32_t al2 = As_lo[ra + 4], al3 = As_lo[rb + 4];
            int kw = ko * 8;
#pragma unroll
            for (int nf = 0; nf < NFRAG; nf++) {
                int nrow = (wn * WN + nf * 8 + g) * PADW + kw + t;
                uint32_t bh0 = wh[nrow], bh1 = wh[nrow + 4];
                uint32_t bl0 = wl[nrow], bl1 = wl[nrow + 4];
                MMA_BF16(c_[nf], ah0, ah1, ah2, ah3, bh0, bh1);
                MMA_BF16(c_[nf], al0, al1, al2, al3, bh0, bh1);
                MMA_BF16(c_[nf], ah0, ah1, ah2, ah3, bl0, bl1);
            }
        }
        __syncthreads();
    }

    // ---- epilogue ------------------------------------------------------------
    int rowa = m0 + wm * 16 + g;
    int rowb = rowa + 8;
#pragma unroll
    for (int nf = 0; nf < NFRAG; nf++) {
        int n = wn * WN + nf * 8 + 2 * t;
        float v0 = c_[nf][0], v1 = c_[nf][1], v2 = c_[nf][2], v3 = c_[nf][3];
        if (HAS_BIAS) {
            float bb0 = bias[n], bb1 = bias[n + 1];
            v0 += bb0; v1 += bb1; v2 += bb0; v3 += bb1;
        }
        if (RELU_OUT) {
            v0 = fmaxf(v0, 0.f); v1 = fmaxf(v1, 0.f);
            v2 = fmaxf(v2, 0.f); v3 = fmaxf(v3, 0.f);
        }
        if (rowa < M) *(float2*)&C[(ll)rowa * BN + n] = make_float2(v0, v1);
        if (rowb < M) *(float2*)&C[(ll)rowb * BN + n] = make_float2(v2, v3);
    }
}

// host-side smem size
static inline int smem_bytes(int BN, int KV) {
    return (2 * 32 * (KV / 2 + 4) + 4 * BN * PADW) * 4;
}

// ---------------- launch ------------------------------------------------------
extern "C" void kernel_launch(void* const* d_in, const int* in_sizes, int n_in,
                              void* d_out, int out_size) {
    const float* x     = (const float*)d_in[0];
    const void*  ei    = d_in[1];
    const float* W_lin = (const float*)d_in[2];
    const float* b_lin = (const float*)d_in[3];
    const float* Wl1   = (const float*)d_in[4];
    const float* bl1   = (const float*)d_in[5];
    const float* Wr1   = (const float*)d_in[6];
    const float* Wl2   = (const float*)d_in[7];
    const float* bl2   = (const float*)d_in[8];
    const float* Wr2   = (const float*)d_in[9];
    const float* W_cls = (const float*)d_in[10];
    float* out = (float*)d_out;

    int n_nodes = in_sizes[0] / IN_F;
    int E       = in_sizes[1] / 2;

    float *h0, *h1, *h2, *mean;
    int *cnt;
    cudaGetSymbolAddress((void**)&h0,   g_h0);
    cudaGetSymbolAddress((void**)&h1,   g_h1);
    cudaGetSymbolAddress((void**)&h2,   g_h2);
    cudaGetSymbolAddress((void**)&mean, g_mean);
    cudaGetSymbolAddress((void**)&cnt,  g_cnt);

    int nb_edges = (E + 255) / 256;
    int nb_gemm  = (n_nodes + 31) / 32;          // 313 blocks

    auto kProj = mma_gemm<HF, 256, false, false, true,  true>;
    auto kSage = mma_gemm<HF, 256, true,  false, false, true>;
    auto kCls  = mma_gemm<NC, 128, false, true,  false, false>;
    int sProj = smem_bytes(HF, 256);
    int sSage = smem_bytes(HF, 256);
    int sCls  = smem_bytes(NC, 128);
    cudaFuncSetAttribute(kProj, cudaFuncAttributeMaxDynamicSharedMemorySize, sProj);
    cudaFuncSetAttribute(kSage, cudaFuncAttributeMaxDynamicSharedMemorySize, sSage);
    cudaFuncSetAttribute(kCls,  cudaFuncAttributeMaxDynamicSharedMemorySize, sCls);

    // Build padded CSR + split weights
    cudaMemsetAsync(cnt, 0, n_nodes * sizeof(int));
    detect_kernel<<<1, 256>>>(ei, (long long)2 * E, n_nodes);
    scatter_kernel<<<nb_edges, 256>>>(ei, E);
    wsplit_kernel<<<(TOTW + 255) / 256, 256>>>(W_lin, Wl1, Wr1, Wl2, Wr2, W_cls);

    // h0 = relu(x @ W_lin^T + b_lin)
    kProj<<<nb_gemm, 256, sProj>>>(x, nullptr, OFF_LIN, 0, b_lin, h0, n_nodes);

    // sage1: mean-agg(h0); h1 = [mean|h0] @ [[Wl1];[Wr1]]^T + bl1
    agg_kernel<<<(n_nodes + 7) / 8, 256>>>(h0, mean, n_nodes);
    kSage<<<nb_gemm, 256, sSage>>>(mean, h0, OFF_L1, OFF_R1, bl1, h1, n_nodes);

    // sage2
    agg_kernel<<<(n_nodes + 7) / 8, 256>>>(h1, mean, n_nodes);
    kSage<<<nb_gemm, 256, sSage>>>(mean, h1, OFF_L2, OFF_R2, bl2, h2, n_nodes);

    // out = relu(h2) @ W_cls^T
    kCls<<<nb_gemm, 256, sCls>>>(h2, nullptr, OFF_CLS, 0, nullptr, out, n_nodes);
}

// round 8
// speedup vs baseline: 1.1516x; 1.1516x over previous
#include <cuda_runtime.h>
#include <cuda_bf16.h>
#include <stdint.h>

#define IN_F 256
#define HF   128
#define NC   64
#define MAX_NODES 10000
#define MAX_EDGES 640000
#define PAD 192   // max supported degree; Poisson(64) tail at 192 is ~1e-60

typedef unsigned long long ull;
typedef long long ll;

// ---------------- scratch (static device globals; no allocation) -------------
__device__ float g_h0[MAX_NODES * HF];
__device__ float g_h1[MAX_NODES * HF];
__device__ float g_h2[MAX_NODES * HF];
__device__ float g_mean[MAX_NODES * HF];
__device__ __nv_bfloat16 g_hb16[MAX_NODES * HF];   // bf16 copy for gather
__device__ int   g_cnt[MAX_NODES];
__device__ int   g_csr[MAX_NODES * PAD];
__device__ int   g_is64;

// Persistent split-bf16 weights
#define OFF_LIN 0
#define OFF_L1  32768
#define OFF_R1  49152
#define OFF_L2  65536
#define OFF_R2  81920
#define OFF_CLS 98304
#define TOTW    106496
__device__ __nv_bfloat16 g_Whi[TOTW];
__device__ __nv_bfloat16 g_Wlo[TOTW];

// ---------------- dtype detect -----------------------------------------------
__global__ void detect_kernel(const void* ei, long long total_elems, int n_nodes) {
    if (threadIdx.x == 0 && blockIdx.x == 0) g_is64 = 1;
    __threadfence();
    const long long* p = (const long long*)ei;
    long long nsamp = total_elems < 4096 ? total_elems : 4096;
    for (long long i = threadIdx.x; i < nsamp; i += blockDim.x) {
        long long v = p[i];
        if (v < 0 || v >= (long long)n_nodes) { g_is64 = 0; break; }
    }
}

// ---------------- padded-CSR scatter -------------------------------------------
__global__ void scatter_kernel(const void* ei, int E) {
    int e = blockIdx.x * blockDim.x + threadIdx.x;
    if (e >= E) return;
    int is64 = g_is64;
    int src, dst;
    if (is64) {
        src = (int)((const long long*)ei)[e];
        dst = (int)((const long long*)ei)[(long long)E + e];
    } else {
        src = ((const int*)ei)[e];
        dst = ((const int*)ei)[E + e];
    }
    int pos = atomicAdd(&g_cnt[dst], 1);
    if (pos < PAD) g_csr[dst * PAD + pos] = src;
}

// ---------------- weight split: fp32 -> bf16 hi + bf16 lo ---------------------
__global__ void wsplit_kernel(const float* __restrict__ wlin,
                              const float* __restrict__ wl1, const float* __restrict__ wr1,
                              const float* __restrict__ wl2, const float* __restrict__ wr2,
                              const float* __restrict__ wcls) {
    int i = blockIdx.x * blockDim.x + threadIdx.x;
    if (i >= TOTW) return;
    const float* src; int off;
    if (i < OFF_L1)       { src = wlin; off = OFF_LIN; }
    else if (i < OFF_L2)  { if (i < OFF_R1) { src = wl1; off = OFF_L1; } else { src = wr1; off = OFF_R1; } }
    else if (i < OFF_CLS) { if (i < OFF_R2) { src = wl2; off = OFF_L2; } else { src = wr2; off = OFF_R2; } }
    else                  { src = wcls; off = OFF_CLS; }
    float x = src[i - off];
    __nv_bfloat16 h = __float2bfloat16_rn(x);
    g_Whi[i] = h;
    g_Wlo[i] = __float2bfloat16_rn(x - __bfloat162float(h));
}

// ---------------- mean aggregation over bf16 copy (warp per node) -------------
// bf16 = truncated fp32: expand via shift/mask, accumulate fp32.
__device__ __forceinline__ float blo(uint32_t u) { return __uint_as_float(u << 16); }
__device__ __forceinline__ float bhi(uint32_t u) { return __uint_as_float(u & 0xffff0000u); }

__global__ void __launch_bounds__(256, 4)
agg_b16(const __nv_bfloat16* __restrict__ hb, float* __restrict__ out, int n) {
    int warp = (blockIdx.x * blockDim.x + threadIdx.x) >> 5;
    int lane = threadIdx.x & 31;
    if (warp >= n) return;
    int deg = g_cnt[warp];
    int end = deg < PAD ? deg : PAD;
    const int* lst = &g_csr[warp * PAD];
    const uint2* p = (const uint2*)hb;   // row = 32 uint2 (4 bf16 each)

    float a00=0,a01=0,a02=0,a03=0, a10=0,a11=0,a12=0,a13=0;
    float a20=0,a21=0,a22=0,a23=0, a30=0,a31=0,a32=0,a33=0;

    int e = 0;
    for (; e + 3 < end; e += 4) {
        int j0 = lst[e], j1 = lst[e+1], j2 = lst[e+2], j3 = lst[e+3];
        uint2 v0 = p[(ll)j0 * 32 + lane];
        uint2 v1 = p[(ll)j1 * 32 + lane];
        uint2 v2 = p[(ll)j2 * 32 + lane];
        uint2 v3 = p[(ll)j3 * 32 + lane];
        a00 += blo(v0.x); a01 += bhi(v0.x); a02 += blo(v0.y); a03 += bhi(v0.y);
        a10 += blo(v1.x); a11 += bhi(v1.x); a12 += blo(v1.y); a13 += bhi(v1.y);
        a20 += blo(v2.x); a21 += bhi(v2.x); a22 += blo(v2.y); a23 += bhi(v2.y);
        a30 += blo(v3.x); a31 += bhi(v3.x); a32 += blo(v3.y); a33 += bhi(v3.y);
    }
    for (; e < end; e++) {
        int j0 = lst[e];
        uint2 v0 = p[(ll)j0 * 32 + lane];
        a00 += blo(v0.x); a01 += bhi(v0.x); a02 += blo(v0.y); a03 += bhi(v0.y);
    }
    float s = 1.0f / (float)(deg > 1 ? deg : 1);
    float4 r = make_float4((a00+a10+a20+a30)*s, (a01+a11+a21+a31)*s,
                           (a02+a12+a22+a32)*s, (a03+a13+a23+a33)*s);
    ((float4*)out)[(ll)warp * 32 + lane] = r;
}

// ---------------- split-bf16 tensor-core GEMM, BM=64, reg-prefetched W --------
#define MMA_BF16(c, a0,a1,a2,a3, b0,b1) \
    asm volatile("mma.sync.aligned.m16n8k16.row.col.f32.bf16.bf16.f32 " \
        "{%0,%1,%2,%3}, {%4,%5,%6,%7}, {%8,%9}, {%0,%1,%2,%3};" \
        : "+f"(c[0]), "+f"(c[1]), "+f"(c[2]), "+f"(c[3]) \
        : "r"(a0), "r"(a1), "r"(a2), "r"(a3), "r"(b0), "r"(b1))

__device__ __forceinline__ uint32_t pk_hi(float a, float b, float& ra, float& rb) {
    __nv_bfloat16 ha = __float2bfloat16_rn(a), hb = __float2bfloat16_rn(b);
    ra = a - __bfloat162float(ha);
    rb = b - __bfloat162float(hb);
    return (uint32_t)__bfloat16_as_ushort(ha) | ((uint32_t)__bfloat16_as_ushort(hb) << 16);
}
__device__ __forceinline__ uint32_t pk_lo(float a, float b) {
    return (uint32_t)__bfloat16_as_ushort(__float2bfloat16_rn(a)) |
           ((uint32_t)__bfloat16_as_ushort(__float2bfloat16_rn(b)) << 16);
}

#define PADW 20   // u32 per 32k W row (16 + 4 pad) -> conflict-free frag LDS

template<int BN, int KV, bool DUAL, bool RELU_IN, bool RELU_OUT, bool HAS_BIAS, bool WB16>
__global__ void __launch_bounds__(256, 2)
mma_gemm(const float* __restrict__ A1, const float* __restrict__ A2,
         int woff1, int woff2,
         const float* __restrict__ bias, float* __restrict__ C,
         __nv_bfloat16* __restrict__ Cb16, int M) {
    const int BM   = 64;
    const int ASTR = KV / 2 + 4;
    const int ASZ  = BM * ASTR;
    const int WBUF = BN * PADW;
    const int NCH  = KV / 32;
    const int KA   = DUAL ? KV / 2 : KV;
    const int NFRAG = BN / 32;
    const int WN    = BN / 4;
    const int NR    = BN / 64;            // uint4 prefetch regs per buffer

    extern __shared__ uint32_t sm[];
    uint32_t* As_hi = sm;
    uint32_t* As_lo = sm + ASZ;
    uint32_t* Wh    = sm + 2 * ASZ;
    uint32_t* Wl    = Wh + WBUF;

    int tid  = threadIdx.x;
    int wid  = tid >> 5;
    int lane = tid & 31;
    int g    = lane >> 2;
    int t    = lane & 3;
    int wm   = wid >> 2;   // 0..1 : 32 rows each
    int wn   = wid & 3;    // 0..3 : WN cols each
    int m0   = blockIdx.x * BM;

    uint4 rh[NR], rl[NR];
    auto ldregs = [&](int c) {
#pragma unroll
        for (int r = 0; r < NR; r++) {
            int f = tid + r * 256;
            int nn = f >> 2, q = f & 3;
            int k = c * 32 + q * 8;
            int wo = woff1, kk = k;
            if (DUAL && k >= KV / 2) { wo = woff2; kk = k - KV / 2; }
            int si = nn * KA + kk + wo;
            rh[r] = *(const uint4*)&g_Whi[si];
            rl[r] = *(const uint4*)&g_Wlo[si];
        }
    };
    auto streg = [&]() {
#pragma unroll
        for (int r = 0; r < NR; r++) {
            int f = tid + r * 256;
            int nn = f >> 2, q = f & 3;
            *(uint4*)&Wh[nn * PADW + q * 4] = rh[r];
            *(uint4*)&Wl[nn * PADW + q * 4] = rl[r];
        }
    };

    ldregs(0);

    // ---- A tile: load, (relu), split, store once ----------------------------
#pragma unroll
    for (int it = 0; it < BM * (KV / 4) / 256; it++) {
        int f = tid + it * 256;
        int m  = f / (KV / 4);
        int kq = f % (KV / 4);
        int k  = kq * 4;
        const float* src = A1; int kk = k;
        if (DUAL && k >= KV / 2) { src = A2; kk = k - KV / 2; }
        float4 v = make_float4(0.f, 0.f, 0.f, 0.f);
        if (m0 + m < M)
            v = *(const float4*)&src[(ll)(m0 + m) * KA + kk];
        if (RELU_IN) {
            v.x = fmaxf(v.x, 0.f); v.y = fmaxf(v.y, 0.f);
            v.z = fmaxf(v.z, 0.f); v.w = fmaxf(v.w, 0.f);
        }
        float rx, ry, rz, rw;
        uint32_t h0 = pk_hi(v.x, v.y, rx, ry);
        uint32_t h1 = pk_hi(v.z, v.w, rz, rw);
        As_hi[m * ASTR + kq * 2 + 0] = h0;
        As_hi[m * ASTR + kq * 2 + 1] = h1;
        As_lo[m * ASTR + kq * 2 + 0] = pk_lo(rx, ry);
        As_lo[m * ASTR + kq * 2 + 1] = pk_lo(rz, rw);
    }

    float c_[2][NFRAG][4];
#pragma unroll
    for (int i = 0; i < 2; i++)
#pragma unroll
        for (int j = 0; j < NFRAG; j++)
#pragma unroll
            for (int q = 0; q < 4; q++) c_[i][j][q] = 0.f;

    streg();
    __syncthreads();

#pragma unroll
    for (int c = 0; c < NCH; c++) {
        if (c + 1 < NCH) ldregs(c + 1);
#pragma unroll
        for (int ko = 0; ko < 2; ko++) {
            int kba = c * 16 + ko * 8;
            int kw  = ko * 8;
            // B fragments for all nf
            uint32_t bh0[NFRAG], bh1[NFRAG], bl0[NFRAG], bl1[NFRAG];
#pragma unroll
            for (int nf = 0; nf < NFRAG; nf++) {
                int nrow = (wn * WN + nf * 8 + g) * PADW + kw + t;
                bh0[nf] = Wh[nrow]; bh1[nf] = Wh[nrow + 4];
                bl0[nf] = Wl[nrow]; bl1[nf] = Wl[nrow + 4];
            }
#pragma unroll
            for (int mf = 0; mf < 2; mf++) {
                int ra = (wm * 32 + mf * 16 + g) * ASTR + kba + t;
                int rb = ra + 8 * ASTR;
                uint32_t ah0 = As_hi[ra],     ah1 = As_hi[rb];
                uint32_t ah2 = As_hi[ra + 4], ah3 = As_hi[rb + 4];
                uint32_t al0 = As_lo[ra],     al1 = As_lo[rb];
                uint32_t al2 = As_lo[ra + 4], al3 = As_lo[rb + 4];
#pragma unroll
                for (int nf = 0; nf < NFRAG; nf++) {
                    MMA_BF16(c_[mf][nf], ah0, ah1, ah2, ah3, bh0[nf], bh1[nf]);
                    MMA_BF16(c_[mf][nf], al0, al1, al2, al3, bh0[nf], bh1[nf]);
                    MMA_BF16(c_[mf][nf], ah0, ah1, ah2, ah3, bl0[nf], bl1[nf]);
                }
            }
        }
        __syncthreads();
        if (c + 1 < NCH) {
            streg();
            __syncthreads();
        }
    }

    // ---- epilogue ------------------------------------------------------------
#pragma unroll
    for (int mf = 0; mf < 2; mf++) {
        int rowa = m0 + wm * 32 + mf * 16 + g;
        int rowb = rowa + 8;
#pragma unroll
        for (int nf = 0; nf < NFRAG; nf++) {
            int n = wn * WN + nf * 8 + 2 * t;
            float v0 = c_[mf][nf][0], v1 = c_[mf][nf][1];
            float v2 = c_[mf][nf][2], v3 = c_[mf][nf][3];
            if (HAS_BIAS) {
                float bb0 = bias[n], bb1 = bias[n + 1];
                v0 += bb0; v1 += bb1; v2 += bb0; v3 += bb1;
            }
            if (RELU_OUT) {
                v0 = fmaxf(v0, 0.f); v1 = fmaxf(v1, 0.f);
                v2 = fmaxf(v2, 0.f); v3 = fmaxf(v3, 0.f);
            }
            if (rowa < M) {
                *(float2*)&C[(ll)rowa * BN + n] = make_float2(v0, v1);
                if (WB16)
                    *(__nv_bfloat162*)&Cb16[(ll)rowa * BN + n] =
                        __nv_bfloat162(__float2bfloat16_rn(v0), __float2bfloat16_rn(v1));
            }
            if (rowb < M) {
                *(float2*)&C[(ll)rowb * BN + n] = make_float2(v2, v3);
                if (WB16)
                    *(__nv_bfloat162*)&Cb16[(ll)rowb * BN + n] =
                        __nv_bfloat162(__float2bfloat16_rn(v2), __float2bfloat16_rn(v3));
            }
        }
    }
}

static inline int smem_bytes(int BN, int KV) {
    return (2 * 64 * (KV / 2 + 4) + 2 * BN * PADW) * 4;
}

// ---------------- launch ------------------------------------------------------
extern "C" void kernel_launch(void* const* d_in, const int* in_sizes, int n_in,
                              void* d_out, int out_size) {
    const float* x     = (const float*)d_in[0];
    const void*  ei    = d_in[1];
    const float* W_lin = (const float*)d_in[2];
    const float* b_lin = (const float*)d_in[3];
    const float* Wl1   = (const float*)d_in[4];
    const float* bl1   = (const float*)d_in[5];
    const float* Wr1   = (const float*)d_in[6];
    const float* Wl2   = (const float*)d_in[7];
    const float* bl2   = (const float*)d_in[8];
    const float* Wr2   = (const float*)d_in[9];
    const float* W_cls = (const float*)d_in[10];
    float* out = (float*)d_out;

    int n_nodes = in_sizes[0] / IN_F;
    int E       = in_sizes[1] / 2;

    float *h0, *h1, *h2, *mean;
    __nv_bfloat16* hb16;
    int *cnt;
    cudaGetSymbolAddress((void**)&h0,   g_h0);
    cudaGetSymbolAddress((void**)&h1,   g_h1);
    cudaGetSymbolAddress((void**)&h2,   g_h2);
    cudaGetSymbolAddress((void**)&mean, g_mean);
    cudaGetSymbolAddress((void**)&hb16, g_hb16);
    cudaGetSymbolAddress((void**)&cnt,  g_cnt);

    int nb_edges = (E + 255) / 256;
    int nb_gemm  = (n_nodes + 63) / 64;          // 157 blocks

    auto kProj = mma_gemm<HF, 256, false, false, true,  true,  true>;
    auto kSg1  = mma_gemm<HF, 256, true,  false, false, true,  true>;
    auto kSg2  = mma_gemm<HF, 256, true,  false, false, true,  false>;
    auto kCls  = mma_gemm<NC, 128, false, true,  false, false, false>;
    int sBig = smem_bytes(HF, 256);
    int sCls = smem_bytes(NC, 128);
    cudaFuncSetAttribute(kProj, cudaFuncAttributeMaxDynamicSharedMemorySize, sBig);
    cudaFuncSetAttribute(kSg1,  cudaFuncAttributeMaxDynamicSharedMemorySize, sBig);
    cudaFuncSetAttribute(kSg2,  cudaFuncAttributeMaxDynamicSharedMemorySize, sBig);
    cudaFuncSetAttribute(kCls,  cudaFuncAttributeMaxDynamicSharedMemorySize, sCls);

    // Build padded CSR + split weights
    cudaMemsetAsync(cnt, 0, n_nodes * sizeof(int));
    detect_kernel<<<1, 256>>>(ei, (long long)2 * E, n_nodes);
    scatter_kernel<<<nb_edges, 256>>>(ei, E);
    wsplit_kernel<<<(TOTW + 255) / 256, 256>>>(W_lin, Wl1, Wr1, Wl2, Wr2, W_cls);

    // h0 = relu(x @ W_lin^T + b_lin), also emits bf16 copy for gather
    kProj<<<nb_gemm, 256, sBig>>>(x, nullptr, OFF_LIN, 0, b_lin, h0, hb16, n_nodes);

    // sage1: mean = agg(h0_b16); h1 = [mean|h0] @ [[Wl1];[Wr1]]^T + bl1 (+ b16 copy)
    agg_b16<<<(n_nodes + 7) / 8, 256>>>(hb16, mean, n_nodes);
    kSg1<<<nb_gemm, 256, sBig>>>(mean, h0, OFF_L1, OFF_R1, bl1, h1, hb16, n_nodes);

    // sage2: mean = agg(h1_b16); h2 = [mean|h1] @ [[Wl2];[Wr2]]^T + bl2
    agg_b16<<<(n_nodes + 7) / 8, 256>>>(hb16, mean, n_nodes);
    kSg2<<<nb_gemm, 256, sBig>>>(mean, h1, OFF_L2, OFF_R2, bl2, h2, nullptr, n_nodes);

    // out = relu(h2) @ W_cls^T
    kCls<<<nb_gemm, 256, sCls>>>(h2, nullptr, OFF_CLS, 0, nullptr, out, nullptr, n_nodes);
}

// round 9
// speedup vs baseline: 1.2577x; 1.0921x over previous
#include <cuda_runtime.h>
#include <cuda_bf16.h>
#include <stdint.h>

#define IN_F 256
#define HF   128
#define NC   64
#define MAX_NODES 10000
#define MAX_EDGES 640000
#define PAD 192   // max supported degree; Poisson(64) tail at 192 is ~1e-60

typedef unsigned long long ull;
typedef long long ll;

// ---------------- scratch (static device globals; no allocation) -------------
__device__ float g_h0[MAX_NODES * HF];
__device__ float g_h1[MAX_NODES * HF];
__device__ float g_h2[MAX_NODES * HF];
__device__ float g_mean[MAX_NODES * HF];
__device__ __nv_bfloat16 g_hb16[MAX_NODES * HF];   // bf16 copy for gather
__device__ int   g_cnt[MAX_NODES];
__device__ int   g_csr[MAX_NODES * PAD];

// Persistent split-bf16 weights
#define OFF_LIN 0
#define OFF_L1  32768
#define OFF_R1  49152
#define OFF_L2  65536
#define OFF_R2  81920
#define OFF_CLS 98304
#define TOTW    106496
__device__ __nv_bfloat16 g_Whi[TOTW];
__device__ __nv_bfloat16 g_Wlo[TOTW];

// ---------------- init: zero counters + split weights --------------------------
__global__ void init_kernel(const float* __restrict__ wlin,
                            const float* __restrict__ wl1, const float* __restrict__ wr1,
                            const float* __restrict__ wl2, const float* __restrict__ wr2,
                            const float* __restrict__ wcls, int n_nodes) {
    int i = blockIdx.x * blockDim.x + threadIdx.x;
    if (i < n_nodes) g_cnt[i] = 0;
    if (i >= TOTW) return;
    const float* src; int off;
    if (i < OFF_L1)       { src = wlin; off = OFF_LIN; }
    else if (i < OFF_L2)  { if (i < OFF_R1) { src = wl1; off = OFF_L1; } else { src = wr1; off = OFF_R1; } }
    else if (i < OFF_CLS) { if (i < OFF_R2) { src = wl2; off = OFF_L2; } else { src = wr2; off = OFF_R2; } }
    else                  { src = wcls; off = OFF_CLS; }
    float x = src[i - off];
    __nv_bfloat16 h = __float2bfloat16_rn(x);
    g_Whi[i] = h;
    g_Wlo[i] = __float2bfloat16_rn(x - __bfloat162float(h));
}

// ---------------- scatter with inline dtype detect -----------------------------
// If edge data is int32, pairs reinterpreted as int64 leave [0, n_nodes) with
// overwhelming probability within 256 samples; __syncthreads_and decides per block.
__global__ void scatter_kernel(const void* ei, int E, int n_nodes) {
    const long long* p64 = (const long long*)ei;
    long long v = p64[threadIdx.x & 255];
    int ok = (v >= 0 && v < (long long)n_nodes) ? 1 : 0;
    int is64 = __syncthreads_and(ok);

    int e = blockIdx.x * blockDim.x + threadIdx.x;
    if (e >= E) return;
    int src, dst;
    if (is64) {
        src = (int)p64[e];
        dst = (int)p64[(ll)E + e];
    } else {
        src = ((const int*)ei)[e];
        dst = ((const int*)ei)[E + e];
    }
    int pos = atomicAdd(&g_cnt[dst], 1);
    if (pos < PAD) g_csr[dst * PAD + pos] = src;
}

// ---------------- mean aggregation over bf16 copy (warp per node) -------------
__device__ __forceinline__ float blo(uint32_t u) { return __uint_as_float(u << 16); }
__device__ __forceinline__ float bhi(uint32_t u) { return __uint_as_float(u & 0xffff0000u); }

__global__ void __launch_bounds__(256, 4)
agg_b16(const __nv_bfloat16* __restrict__ hb, float* __restrict__ out, int n) {
    int warp = (blockIdx.x * blockDim.x + threadIdx.x) >> 5;
    int lane = threadIdx.x & 31;
    if (warp >= n) return;
    int deg = g_cnt[warp];
    int end = deg < PAD ? deg : PAD;
    const int* lst = &g_csr[warp * PAD];
    const uint2* p = (const uint2*)hb;   // row = 32 uint2 (4 bf16 each)

    float a00=0,a01=0,a02=0,a03=0, a10=0,a11=0,a12=0,a13=0;
    float a20=0,a21=0,a22=0,a23=0, a30=0,a31=0,a32=0,a33=0;

    int e = 0;
    for (; e + 3 < end; e += 4) {
        int j0 = lst[e], j1 = lst[e+1], j2 = lst[e+2], j3 = lst[e+3];
        uint2 v0 = p[(ll)j0 * 32 + lane];
        uint2 v1 = p[(ll)j1 * 32 + lane];
        uint2 v2 = p[(ll)j2 * 32 + lane];
        uint2 v3 = p[(ll)j3 * 32 + lane];
        a00 += blo(v0.x); a01 += bhi(v0.x); a02 += blo(v0.y); a03 += bhi(v0.y);
        a10 += blo(v1.x); a11 += bhi(v1.x); a12 += blo(v1.y); a13 += bhi(v1.y);
        a20 += blo(v2.x); a21 += bhi(v2.x); a22 += blo(v2.y); a23 += bhi(v2.y);
        a30 += blo(v3.x); a31 += bhi(v3.x); a32 += blo(v3.y); a33 += bhi(v3.y);
    }
    for (; e < end; e++) {
        int j0 = lst[e];
        uint2 v0 = p[(ll)j0 * 32 + lane];
        a00 += blo(v0.x); a01 += bhi(v0.x); a02 += blo(v0.y); a03 += bhi(v0.y);
    }
    float s = 1.0f / (float)(deg > 1 ? deg : 1);
    float4 r = make_float4((a00+a10+a20+a30)*s, (a01+a11+a21+a31)*s,
                           (a02+a12+a22+a32)*s, (a03+a13+a23+a33)*s);
    ((float4*)out)[(ll)warp * 32 + lane] = r;
}

// ---------------- split-bf16 MMA GEMM: BM=64, BN=64 per block, ldmatrix -------
#define MMA_BF16(c, a0,a1,a2,a3, b0,b1) \
    asm volatile("mma.sync.aligned.m16n8k16.row.col.f32.bf16.bf16.f32 " \
        "{%0,%1,%2,%3}, {%4,%5,%6,%7}, {%8,%9}, {%0,%1,%2,%3};" \
        : "+f"(c[0]), "+f"(c[1]), "+f"(c[2]), "+f"(c[3]) \
        : "r"(a0), "r"(a1), "r"(a2), "r"(a3), "r"(b0), "r"(b1))

#define LDSM_X4(r0,r1,r2,r3, addr) \
    asm volatile("ldmatrix.sync.aligned.m8n8.x4.shared.b16 {%0,%1,%2,%3}, [%4];" \
        : "=r"(r0), "=r"(r1), "=r"(r2), "=r"(r3) : "r"(addr))
#define LDSM_X2(r0,r1, addr) \
    asm volatile("ldmatrix.sync.aligned.m8n8.x2.shared.b16 {%0,%1}, [%2];" \
        : "=r"(r0), "=r"(r1) : "r"(addr))

__device__ __forceinline__ uint32_t pk_hi(float a, float b, float& ra, float& rb) {
    __nv_bfloat16 ha = __float2bfloat16_rn(a), hb = __float2bfloat16_rn(b);
    ra = a - __bfloat162float(ha);
    rb = b - __bfloat162float(hb);
    return (uint32_t)__bfloat16_as_ushort(ha) | ((uint32_t)__bfloat16_as_ushort(hb) << 16);
}
__device__ __forceinline__ uint32_t pk_lo(float a, float b) {
    return (uint32_t)__bfloat16_as_ushort(__float2bfloat16_rn(a)) |
           ((uint32_t)__bfloat16_as_ushort(__float2bfloat16_rn(b)) << 16);
}

#define PADW 20   // u32 per 32k W row (16 + 4 pad)

// KN = full output width (row stride of C); block covers 64 columns at n0.
template<int KN, int KV, bool DUAL, bool RELU_IN, bool RELU_OUT, bool HAS_BIAS, bool WB16>
__global__ void __launch_bounds__(256, 2)
mma_gemm(const float* __restrict__ A1, const float* __restrict__ A2,
         int woff1, int woff2,
         const float* __restrict__ bias, float* __restrict__ C,
         __nv_bfloat16* __restrict__ Cb16, int M) {
    const int BM   = 64;
    const int ASTR = KV / 2 + 4;          // u32 per A row
    const int ASZ  = BM * ASTR;
    const int WBUF = 64 * PADW;
    const int NCH  = KV / 32;
    const int KA   = DUAL ? KV / 2 : KV;

    extern __shared__ uint32_t sm[];
    uint32_t* As_hi = sm;
    uint32_t* As_lo = sm + ASZ;
    uint32_t* Wh    = sm + 2 * ASZ;
    uint32_t* Wl    = Wh + WBUF;

    int tid  = threadIdx.x;
    int wid  = tid >> 5;
    int lane = tid & 31;
    int g    = lane >> 2;
    int t    = lane & 3;
    int wm   = wid >> 2;   // 0..1 : 32 rows each
    int wn   = wid & 3;    // 0..3 : 16 cols each
    int m0   = blockIdx.x * BM;
    int n0   = blockIdx.y * 64;

    // W chunk register prefetch (1 uint4 pair per thread covers 64x32 chunk)
    uint4 rh, rl;
    int w_nn = tid >> 2, w_q = tid & 3;
    auto ldregs = [&](int c) {
        int k = c * 32 + w_q * 8;
        int wo = woff1, kk = k;
        if (DUAL && k >= KV / 2) { wo = woff2; kk = k - KV / 2; }
        int si = (n0 + w_nn) * KA + kk + wo;
        rh = *(const uint4*)&g_Whi[si];
        rl = *(const uint4*)&g_Wlo[si];
    };
    auto streg = [&]() {
        *(uint4*)&Wh[w_nn * PADW + w_q * 4] = rh;
        *(uint4*)&Wl[w_nn * PADW + w_q * 4] = rl;
    };

    ldregs(0);

    // ---- A tile: load, (relu), split, store once ----------------------------
#pragma unroll
    for (int it = 0; it < BM * (KV / 4) / 256; it++) {
        int f = tid + it * 256;
        int m  = f / (KV / 4);
        int kq = f % (KV / 4);
        int k  = kq * 4;
        const float* src = A1; int kk = k;
        if (DUAL && k >= KV / 2) { src = A2; kk = k - KV / 2; }
        float4 v = make_float4(0.f, 0.f, 0.f, 0.f);
        if (m0 + m < M)
            v = *(const float4*)&src[(ll)(m0 + m) * KA + kk];
        if (RELU_IN) {
            v.x = fmaxf(v.x, 0.f); v.y = fmaxf(v.y, 0.f);
            v.z = fmaxf(v.z, 0.f); v.w = fmaxf(v.w, 0.f);
        }
        float rx, ry, rz, rw;
        uint32_t h0 = pk_hi(v.x, v.y, rx, ry);
        uint32_t h1 = pk_hi(v.z, v.w, rz, rw);
        As_hi[m * ASTR + kq * 2 + 0] = h0;
        As_hi[m * ASTR + kq * 2 + 1] = h1;
        As_lo[m * ASTR + kq * 2 + 0] = pk_lo(rx, ry);
        As_lo[m * ASTR + kq * 2 + 1] = pk_lo(rz, rw);
    }

    // ldmatrix per-thread address precomputation
    uint32_t aHiB = (uint32_t)__cvta_generic_to_shared(As_hi);
    uint32_t aLoB = (uint32_t)__cvta_generic_to_shared(As_lo);
    uint32_t wHiB = (uint32_t)__cvta_generic_to_shared(Wh);
    uint32_t wLoB = (uint32_t)__cvta_generic_to_shared(Wl);
    int amat = lane >> 3, ar = lane & 7;
    uint32_t aOff[2];
#pragma unroll
    for (int mf = 0; mf < 2; mf++)
        aOff[mf] = (uint32_t)((wm * 32 + mf * 16 + (amat & 1) * 8 + ar) * (ASTR * 4)
                              + (amat >> 1) * 16);
    int blx = lane & 15;
    int bmat = blx >> 3, br = blx & 7;
    uint32_t bOff[2];
#pragma unroll
    for (int nf = 0; nf < 2; nf++)
        bOff[nf] = (uint32_t)((wn * 16 + nf * 8 + br) * (PADW * 4) + bmat * 16);

    float c_[2][2][4];
#pragma unroll
    for (int i = 0; i < 2; i++)
#pragma unroll
        for (int j = 0; j < 2; j++)
#pragma unroll
            for (int q = 0; q < 4; q++) c_[i][j][q] = 0.f;

    streg();
    __syncthreads();

#pragma unroll
    for (int c = 0; c < NCH; c++) {
        if (c + 1 < NCH) ldregs(c + 1);
#pragma unroll
        for (int ko = 0; ko < 2; ko++) {
            uint32_t kbyte = (uint32_t)((c * 16 + ko * 8) * 4);
            uint32_t kwb   = (uint32_t)(ko * 8 * 4);
            uint32_t bh0[2], bh1[2], bl0[2], bl1[2];
#pragma unroll
            for (int nf = 0; nf < 2; nf++) {
                LDSM_X2(bh0[nf], bh1[nf], wHiB + bOff[nf] + kwb);
                LDSM_X2(bl0[nf], bl1[nf], wLoB + bOff[nf] + kwb);
            }
#pragma unroll
            for (int mf = 0; mf < 2; mf++) {
                uint32_t ah0, ah1, ah2, ah3, al0, al1, al2, al3;
                LDSM_X4(ah0, ah1, ah2, ah3, aHiB + aOff[mf] + kbyte);
                LDSM_X4(al0, al1, al2, al3, aLoB + aOff[mf] + kbyte);
#pragma unroll
                for (int nf = 0; nf < 2; nf++) {
                    MMA_BF16(c_[mf][nf], ah0, ah1, ah2, ah3, bh0[nf], bh1[nf]);
                    MMA_BF16(c_[mf][nf], al0, al1, al2, al3, bh0[nf], bh1[nf]);
                    MMA_BF16(c_[mf][nf], ah0, ah1, ah2, ah3, bl0[nf], bl1[nf]);
                }
            }
        }
        __syncthreads();
        if (c + 1 < NCH) {
            streg();
            __syncthreads();
        }
    }

    // ---- epilogue ------------------------------------------------------------
#pragma unroll
    for (int mf = 0; mf < 2; mf++) {
        int rowa = m0 + wm * 32 + mf * 16 + g;
        int rowb = rowa + 8;
#pragma unroll
        for (int nf = 0; nf < 2; nf++) {
            int n = n0 + wn * 16 + nf * 8 + 2 * t;
            float v0 = c_[mf][nf][0], v1 = c_[mf][nf][1];
            float v2 = c_[mf][nf][2], v3 = c_[mf][nf][3];
            if (HAS_BIAS) {
                float bb0 = bias[n], bb1 = bias[n + 1];
                v0 += bb0; v1 += bb1; v2 += bb0; v3 += bb1;
            }
            if (RELU_OUT) {
                v0 = fmaxf(v0, 0.f); v1 = fmaxf(v1, 0.f);
                v2 = fmaxf(v2, 0.f); v3 = fmaxf(v3, 0.f);
            }
            if (rowa < M) {
                *(float2*)&C[(ll)rowa * KN + n] = make_float2(v0, v1);
                if (WB16)
                    *(__nv_bfloat162*)&Cb16[(ll)rowa * KN + n] =
                        __nv_bfloat162(__float2bfloat16_rn(v0), __float2bfloat16_rn(v1));
            }
            if (rowb < M) {
                *(float2*)&C[(ll)rowb * KN + n] = make_float2(v2, v3);
                if (WB16)
                    *(__nv_bfloat162*)&Cb16[(ll)rowb * KN + n] =
                        __nv_bfloat162(__float2bfloat16_rn(v2), __float2bfloat16_rn(v3));
            }
        }
    }
}

static inline int smem_bytes(int KV) {
    return (2 * 64 * (KV / 2 + 4) + 2 * 64 * PADW) * 4;
}

// ---------------- launch ------------------------------------------------------
extern "C" void kernel_launch(void* const* d_in, const int* in_sizes, int n_in,
                              void* d_out, int out_size) {
    const float* x     = (const float*)d_in[0];
    const void*  ei    = d_in[1];
    const float* W_lin = (const float*)d_in[2];
    const float* b_lin = (const float*)d_in[3];
    const float* Wl1   = (const float*)d_in[4];
    const float* bl1   = (const float*)d_in[5];
    const float* Wr1   = (const float*)d_in[6];
    const float* Wl2   = (const float*)d_in[7];
    const float* bl2   = (const float*)d_in[8];
    const float* Wr2   = (const float*)d_in[9];
    const float* W_cls = (const float*)d_in[10];
    float* out = (float*)d_out;

    int n_nodes = in_sizes[0] / IN_F;
    int E       = in_sizes[1] / 2;

    float *h0, *h1, *h2, *mean;
    __nv_bfloat16* hb16;
    cudaGetSymbolAddress((void**)&h0,   g_h0);
    cudaGetSymbolAddress((void**)&h1,   g_h1);
    cudaGetSymbolAddress((void**)&h2,   g_h2);
    cudaGetSymbolAddress((void**)&mean, g_mean);
    cudaGetSymbolAddress((void**)&hb16, g_hb16);

    int nb_edges = (E + 255) / 256;
    dim3 gH((n_nodes + 63) / 64, 2);   // 157 x 2 = 314 blocks (KN=128)
    dim3 gC((n_nodes + 63) / 64, 1);   // cls (KN=64)

    auto kProj = mma_gemm<HF, 256, false, false, true,  true,  true>;
    auto kSg1  = mma_gemm<HF, 256, true,  false, false, true,  true>;
    auto kSg2  = mma_gemm<HF, 256, true,  false, false, true,  false>;
    auto kCls  = mma_gemm<NC, 128, false, true,  false, false, false>;
    int sBig = smem_bytes(256);
    int sCls = smem_bytes(128);
    cudaFuncSetAttribute(kProj, cudaFuncAttributeMaxDynamicSharedMemorySize, sBig);
    cudaFuncSetAttribute(kSg1,  cudaFuncAttributeMaxDynamicSharedMemorySize, sBig);
    cudaFuncSetAttribute(kSg2,  cudaFuncAttributeMaxDynamicSharedMemorySize, sBig);
    cudaFuncSetAttribute(kCls,  cudaFuncAttributeMaxDynamicSharedMemorySize, sCls);

    // init (cnt zero + weight split), then CSR scatter w/ inline dtype detect
    init_kernel<<<(TOTW + 255) / 256, 256>>>(W_lin, Wl1, Wr1, Wl2, Wr2, W_cls, n_nodes);
    scatter_kernel<<<nb_edges, 256>>>(ei, E, n_nodes);

    // h0 = relu(x @ W_lin^T + b_lin) (+ bf16 copy)
    kProj<<<gH, 256, sBig>>>(x, nullptr, OFF_LIN, 0, b_lin, h0, hb16, n_nodes);

    // sage1: mean = agg(h0_b16); h1 = [mean|h0] @ [[Wl1];[Wr1]]^T + bl1 (+ b16)
    agg_b16<<<(n_nodes + 7) / 8, 256>>>(hb16, mean, n_nodes);
    kSg1<<<gH, 256, sBig>>>(mean, h0, OFF_L1, OFF_R1, bl1, h1, hb16, n_nodes);

    // sage2: mean = agg(h1_b16); h2 = [mean|h1] @ [[Wl2];[Wr2]]^T + bl2
    agg_b16<<<(n_nodes + 7) / 8, 256>>>(hb16, mean, n_nodes);
    kSg2<<<gH, 256, sBig>>>(mean, h1, OFF_L2, OFF_R2, bl2, h2, nullptr, n_nodes);

    // out = relu(h2) @ W_cls^T
    kCls<<<gC, 256, sCls>>>(h2, nullptr, OFF_CLS, 0, nullptr, out, nullptr, n_nodes);
}